// round 1
// baseline (speedup 1.0000x reference)
#include <cuda_runtime.h>
#include <math.h>

// Problem constants
#define BB 4
#define TT 2048
#define CC 1024
#define HH 16
#define HS 64
#define FF 4096
#define MROWS (BB * TT)   // 8192

// ---------------------------------------------------------------------------
// Scratch (device globals; no allocation allowed in kernel_launch)
// ---------------------------------------------------------------------------
__device__ float g_q [BB * TT * CC];
__device__ float g_k [BB * TT * CC];
__device__ float g_v [BB * TT * CC];
__device__ float g_y [BB * TT * CC];
__device__ float g_x2[BB * TT * CC];
__device__ float g_h1[BB * TT * FF];

// ---------------------------------------------------------------------------
// Generic tiled SGEMM: C[M,N] = A[M,K] * B  (+bias)(+res)(relu)
// Block tile 128x128, thread tile 8x8, K-chunk 8, 256 threads.
// MODE 0: B is plain row-major [K, N]
// MODE 1: B is per-head weights [H, K, 64]; column n -> head n>>6, d = n&63
// ---------------------------------------------------------------------------
template <int MODE, bool RELU, bool BIAS, bool RES>
__global__ __launch_bounds__(256) void sgemm_kernel(
    const float* __restrict__ A, const float* __restrict__ B,
    const float* __restrict__ bias, const float* __restrict__ res,
    float* __restrict__ C, int M, int N, int K)
{
    __shared__ float Ast[8][132];   // [kk][row], padded
    __shared__ float Bs [8][132];   // [kk][col], padded

    const int tid = threadIdx.x;
    const int tx = tid & 15;        // 0..15 -> col groups
    const int ty = tid >> 4;        // 0..15 -> row groups
    const int rowBase = blockIdx.y * 128;
    const int colBase = blockIdx.x * 128;

    float acc[8][8];
#pragma unroll
    for (int i = 0; i < 8; i++)
#pragma unroll
        for (int j = 0; j < 8; j++) acc[i][j] = 0.0f;

    const int ar = tid >> 1;         // 0..127 : A row within tile
    const int ah = (tid & 1) * 4;    // 0 or 4 : k offset
    const int bc = (tid & 31) * 4;   // 0..124 : B col within tile
    const int bk = tid >> 5;         // 0..7   : B k within chunk

    for (int k0 = 0; k0 < K; k0 += 8) {
        float4 a4 = *reinterpret_cast<const float4*>(
            &A[(size_t)(rowBase + ar) * K + k0 + ah]);
        float4 b4;
        if (MODE == 0) {
            b4 = *reinterpret_cast<const float4*>(
                &B[(size_t)(k0 + bk) * N + colBase + bc]);
        } else {
            int n = colBase + bc;
            b4 = *reinterpret_cast<const float4*>(
                &B[(size_t)(n >> 6) * K * 64 + (size_t)(k0 + bk) * 64 + (n & 63)]);
        }
        __syncthreads();            // previous compute done before overwrite
        Ast[ah + 0][ar] = a4.x;
        Ast[ah + 1][ar] = a4.y;
        Ast[ah + 2][ar] = a4.z;
        Ast[ah + 3][ar] = a4.w;
        *reinterpret_cast<float4*>(&Bs[bk][bc]) = b4;
        __syncthreads();

#pragma unroll
        for (int kk = 0; kk < 8; kk++) {
            float4 a0 = *reinterpret_cast<float4*>(&Ast[kk][ty * 8]);
            float4 a1 = *reinterpret_cast<float4*>(&Ast[kk][ty * 8 + 4]);
            float4 b0 = *reinterpret_cast<float4*>(&Bs[kk][tx * 8]);
            float4 b1 = *reinterpret_cast<float4*>(&Bs[kk][tx * 8 + 4]);
            float ra[8] = {a0.x, a0.y, a0.z, a0.w, a1.x, a1.y, a1.z, a1.w};
            float rb[8] = {b0.x, b0.y, b0.z, b0.w, b1.x, b1.y, b1.z, b1.w};
#pragma unroll
            for (int i = 0; i < 8; i++)
#pragma unroll
                for (int j = 0; j < 8; j++)
                    acc[i][j] = fmaf(ra[i], rb[j], acc[i][j]);
        }
    }

#pragma unroll
    for (int i = 0; i < 8; i++) {
        int row = rowBase + ty * 8 + i;
#pragma unroll
        for (int j = 0; j < 8; j++) {
            int col = colBase + tx * 8 + j;
            float val = acc[i][j];
            if (BIAS) val += bias[col];
            if (RES)  val += res[(size_t)row * N + col];
            if (RELU) val = fmaxf(val, 0.0f);
            C[(size_t)row * N + col] = val;
        }
    }
}

// ---------------------------------------------------------------------------
// Flash-style causal attention.
// q,k,v,y layout: [B, T, H*HS] (contiguous per (b,t): heads concat)
// Block: 64 query rows x one (b,h). Key tiles of 32. 256 threads (16x16).
// Thread owns 4 rows (ty) x {2 score cols / 4 out dims} (tx).
// ---------------------------------------------------------------------------
__global__ __launch_bounds__(256) void attn_kernel(
    const float* __restrict__ q, const float* __restrict__ k,
    const float* __restrict__ v, float* __restrict__ y)
{
    __shared__ float Qst[64][65];  // [d][row]
    __shared__ float Kst[64][33];  // [d][scol]
    __shared__ float Vs [32][65];  // [srow][d]
    __shared__ float Pst[32][65];  // [s][row]

    const int tid = threadIdx.x;
    const int tx = tid & 15;
    const int ty = tid >> 4;
    const int bh = blockIdx.y;
    const int b  = bh >> 4;
    const int h  = bh & 15;
    const int t0 = blockIdx.x * 64;
    const float scale = 0.03125f;  // 1024^-0.5

    const size_t base = ((size_t)b * TT) * CC + h * 64;

    // Load Q tile (scaled), transposed: Qst[d][r]
    {
        int d = tid & 63, r0 = tid >> 6;
#pragma unroll
        for (int r = r0; r < 64; r += 4)
            Qst[d][r] = q[base + (size_t)(t0 + r) * CC + d] * scale;
    }

    float m_i[4], l_i[4], acc[4][4];
#pragma unroll
    for (int i = 0; i < 4; i++) {
        m_i[i] = -1e30f;
        l_i[i] = 0.0f;
#pragma unroll
        for (int j = 0; j < 4; j++) acc[i][j] = 0.0f;
    }

    const int ntiles = t0 / 32 + 2;
    for (int it = 0; it < ntiles; it++) {
        const int s0 = it * 32;
        __syncthreads();
        // Load K (transposed) and V tiles
        {
            int d = tid & 63, sc0 = tid >> 6;
#pragma unroll
            for (int sc = sc0; sc < 32; sc += 4) {
                Kst[d][sc] = k[base + (size_t)(s0 + sc) * CC + d];
                Vs[sc][d]  = v[base + (size_t)(s0 + sc) * CC + d];
            }
        }
        __syncthreads();

        // S = Q K^T  (64 x 32 tile; thread: 4 rows x 2 cols)
        float s[4][2];
#pragma unroll
        for (int i = 0; i < 4; i++) { s[i][0] = 0.0f; s[i][1] = 0.0f; }
#pragma unroll 8
        for (int d = 0; d < 64; d++) {
            float qa0 = Qst[d][ty * 4 + 0];
            float qa1 = Qst[d][ty * 4 + 1];
            float qa2 = Qst[d][ty * 4 + 2];
            float qa3 = Qst[d][ty * 4 + 3];
            float kb0 = Kst[d][tx * 2 + 0];
            float kb1 = Kst[d][tx * 2 + 1];
            s[0][0] = fmaf(qa0, kb0, s[0][0]); s[0][1] = fmaf(qa0, kb1, s[0][1]);
            s[1][0] = fmaf(qa1, kb0, s[1][0]); s[1][1] = fmaf(qa1, kb1, s[1][1]);
            s[2][0] = fmaf(qa2, kb0, s[2][0]); s[2][1] = fmaf(qa2, kb1, s[2][1]);
            s[3][0] = fmaf(qa3, kb0, s[3][0]); s[3][1] = fmaf(qa3, kb1, s[3][1]);
        }

        // Causal mask (only the last two tiles can cross the diagonal)
        if (s0 + 31 > t0) {
#pragma unroll
            for (int i = 0; i < 4; i++)
#pragma unroll
                for (int j = 0; j < 2; j++)
                    if (s0 + tx * 2 + j > t0 + ty * 4 + i) s[i][j] = -1e30f;
        }

        // Online softmax update
        float alpha[4];
#pragma unroll
        for (int i = 0; i < 4; i++) {
            float tm = fmaxf(s[i][0], s[i][1]);
            tm = fmaxf(tm, __shfl_xor_sync(0xffffffffu, tm, 1));
            tm = fmaxf(tm, __shfl_xor_sync(0xffffffffu, tm, 2));
            tm = fmaxf(tm, __shfl_xor_sync(0xffffffffu, tm, 4));
            tm = fmaxf(tm, __shfl_xor_sync(0xffffffffu, tm, 8));
            float mn = fmaxf(m_i[i], tm);
            alpha[i] = __expf(m_i[i] - mn);
            m_i[i] = mn;
            float p0 = __expf(s[i][0] - mn);
            float p1 = __expf(s[i][1] - mn);
            s[i][0] = p0; s[i][1] = p1;
            float rs = p0 + p1;
            rs += __shfl_xor_sync(0xffffffffu, rs, 1);
            rs += __shfl_xor_sync(0xffffffffu, rs, 2);
            rs += __shfl_xor_sync(0xffffffffu, rs, 4);
            rs += __shfl_xor_sync(0xffffffffu, rs, 8);
            l_i[i] = l_i[i] * alpha[i] + rs;
        }
#pragma unroll
        for (int i = 0; i < 4; i++)
#pragma unroll
            for (int j = 0; j < 4; j++) acc[i][j] *= alpha[i];

        // P to shared (transposed: Pst[s][row])
#pragma unroll
        for (int i = 0; i < 4; i++)
#pragma unroll
            for (int j = 0; j < 2; j++)
                Pst[tx * 2 + j][ty * 4 + i] = s[i][j];
        __syncthreads();

        // O += P @ V   (thread: 4 rows x 4 dims)
#pragma unroll 4
        for (int ss = 0; ss < 32; ss++) {
            float pa0 = Pst[ss][ty * 4 + 0];
            float pa1 = Pst[ss][ty * 4 + 1];
            float pa2 = Pst[ss][ty * 4 + 2];
            float pa3 = Pst[ss][ty * 4 + 3];
            float vb0 = Vs[ss][tx * 4 + 0];
            float vb1 = Vs[ss][tx * 4 + 1];
            float vb2 = Vs[ss][tx * 4 + 2];
            float vb3 = Vs[ss][tx * 4 + 3];
            acc[0][0] = fmaf(pa0, vb0, acc[0][0]); acc[0][1] = fmaf(pa0, vb1, acc[0][1]);
            acc[0][2] = fmaf(pa0, vb2, acc[0][2]); acc[0][3] = fmaf(pa0, vb3, acc[0][3]);
            acc[1][0] = fmaf(pa1, vb0, acc[1][0]); acc[1][1] = fmaf(pa1, vb1, acc[1][1]);
            acc[1][2] = fmaf(pa1, vb2, acc[1][2]); acc[1][3] = fmaf(pa1, vb3, acc[1][3]);
            acc[2][0] = fmaf(pa2, vb0, acc[2][0]); acc[2][1] = fmaf(pa2, vb1, acc[2][1]);
            acc[2][2] = fmaf(pa2, vb2, acc[2][2]); acc[2][3] = fmaf(pa2, vb3, acc[2][3]);
            acc[3][0] = fmaf(pa3, vb0, acc[3][0]); acc[3][1] = fmaf(pa3, vb1, acc[3][1]);
            acc[3][2] = fmaf(pa3, vb2, acc[3][2]); acc[3][3] = fmaf(pa3, vb3, acc[3][3]);
        }
    }

    // Normalize and store: y[b, t, h*64 + d]
#pragma unroll
    for (int i = 0; i < 4; i++) {
        float inv = 1.0f / l_i[i];
        int t = t0 + ty * 4 + i;
#pragma unroll
        for (int j = 0; j < 4; j++)
            y[base + (size_t)t * CC + tx * 4 + j] = acc[i][j] * inv;
    }
}

// ---------------------------------------------------------------------------
// Launch: QKV (3x head-GEMM) -> attention -> proj+res -> FF1 relu -> FF2+res
// ---------------------------------------------------------------------------
extern "C" void kernel_launch(void* const* d_in, const int* in_sizes, int n_in,
                              void* d_out, int out_size)
{
    const float* x     = (const float*)d_in[0];
    const float* Wq    = (const float*)d_in[1];
    const float* Wk    = (const float*)d_in[2];
    const float* Wv    = (const float*)d_in[3];
    const float* Wproj = (const float*)d_in[4];
    const float* bproj = (const float*)d_in[5];
    const float* W1    = (const float*)d_in[6];
    const float* b1    = (const float*)d_in[7];
    const float* W2    = (const float*)d_in[8];
    const float* b2    = (const float*)d_in[9];
    float* out = (float*)d_out;

    float *qp, *kp, *vp, *yp, *x2p, *h1p;
    cudaGetSymbolAddress((void**)&qp,  g_q);
    cudaGetSymbolAddress((void**)&kp,  g_k);
    cudaGetSymbolAddress((void**)&vp,  g_v);
    cudaGetSymbolAddress((void**)&yp,  g_y);
    cudaGetSymbolAddress((void**)&x2p, g_x2);
    cudaGetSymbolAddress((void**)&h1p, g_h1);

    dim3 tpb(256);
    dim3 g1024(CC / 128, MROWS / 128);   // (8, 64)
    dim3 g4096(FF / 128, MROWS / 128);   // (32, 64)

    // QKV projections (per-head weight layout)
    sgemm_kernel<1, false, false, false><<<g1024, tpb>>>(x, Wq, nullptr, nullptr, qp, MROWS, CC, CC);
    sgemm_kernel<1, false, false, false><<<g1024, tpb>>>(x, Wk, nullptr, nullptr, kp, MROWS, CC, CC);
    sgemm_kernel<1, false, false, false><<<g1024, tpb>>>(x, Wv, nullptr, nullptr, vp, MROWS, CC, CC);

    // Causal attention
    attn_kernel<<<dim3(TT / 64, BB * HH), tpb>>>(qp, kp, vp, yp);

    // Output projection + bias + residual(x)
    sgemm_kernel<0, false, true, true><<<g1024, tpb>>>(yp, Wproj, bproj, x, x2p, MROWS, CC, CC);

    // FF1: relu(x2 @ W1 + b1)
    sgemm_kernel<0, true, true, false><<<g4096, tpb>>>(x2p, W1, b1, nullptr, h1p, MROWS, FF, CC);

    // FF2: h1 @ W2 + b2 + x2
    sgemm_kernel<0, false, true, true><<<g1024, tpb>>>(h1p, W2, b2, x2p, out, MROWS, CC, FF);
}

// round 3
// speedup vs baseline: 1.7470x; 1.7470x over previous
#include <cuda_runtime.h>
#include <cuda_bf16.h>
#include <cstdint>

// Problem constants
#define BB 4
#define TT 2048
#define CC 1024
#define HH 16
#define FF 4096
#define MROWS 8192

// ---------------------------------------------------------------------------
// PTX helpers (sm_103 base-compatible: cp.async, ldmatrix, mma.sync)
// ---------------------------------------------------------------------------
__device__ __forceinline__ uint32_t smem_u32(const void* p) {
    uint32_t a;
    asm("{ .reg .u64 t; cvta.to.shared.u64 t, %1; cvt.u32.u64 %0, t; }" : "=r"(a) : "l"(p));
    return a;
}

__device__ __forceinline__ void cp_async16(uint32_t s, const void* g) {
    asm volatile("cp.async.cg.shared.global [%0], [%1], 16;" :: "r"(s), "l"(g) : "memory");
}
#define CP_COMMIT() asm volatile("cp.async.commit_group;" ::: "memory")
#define CP_WAIT(n)  asm volatile("cp.async.wait_group %0;" :: "n"(n) : "memory")

__device__ __forceinline__ void ldsm_x4(uint32_t* r, uint32_t addr) {
    asm volatile("ldmatrix.sync.aligned.m8n8.x4.shared.b16 {%0,%1,%2,%3}, [%4];"
                 : "=r"(r[0]), "=r"(r[1]), "=r"(r[2]), "=r"(r[3]) : "r"(addr));
}

__device__ __forceinline__ void mma_bf16(float* c, const uint32_t* a, const uint32_t* b) {
    asm volatile(
        "mma.sync.aligned.m16n8k16.row.col.f32.bf16.bf16.f32 "
        "{%0,%1,%2,%3}, {%4,%5,%6,%7}, {%8,%9}, {%0,%1,%2,%3};"
        : "+f"(c[0]), "+f"(c[1]), "+f"(c[2]), "+f"(c[3])
        : "r"(a[0]), "r"(a[1]), "r"(a[2]), "r"(a[3]), "r"(b[0]), "r"(b[1]));
}

// ---------------------------------------------------------------------------
// Scratch buffers (device globals)
// ---------------------------------------------------------------------------
__device__ __nv_bfloat16 g_xhi[MROWS * CC],  g_xlo[MROWS * CC];
__device__ __nv_bfloat16 g_Bqkv_hi[3072 * CC], g_Bqkv_lo[3072 * CC];
__device__ __nv_bfloat16 g_Bp_hi[CC * CC],   g_Bp_lo[CC * CC];
__device__ __nv_bfloat16 g_B1_hi[FF * CC],   g_B1_lo[FF * CC];
__device__ __nv_bfloat16 g_B2_hi[CC * FF],   g_B2_lo[CC * FF];
__device__ float         g_qkv[MROWS * 3072];
__device__ __nv_bfloat16 g_yhi[MROWS * CC],  g_ylo[MROWS * CC];
__device__ float         g_x2[MROWS * CC];
__device__ __nv_bfloat16 g_x2hi[MROWS * CC], g_x2lo[MROWS * CC];
__device__ __nv_bfloat16 g_h1hi[MROWS * FF], g_h1lo[MROWS * FF];

// ---------------------------------------------------------------------------
// fp32 -> bf16 hi/lo split (elementwise, float4)
// ---------------------------------------------------------------------------
__global__ __launch_bounds__(256) void conv_split(
    const float* __restrict__ in, __nv_bfloat16* __restrict__ hi,
    __nv_bfloat16* __restrict__ lo, int n4)
{
    int i = blockIdx.x * 256 + threadIdx.x;
    if (i >= n4) return;
    float4 v = reinterpret_cast<const float4*>(in)[i];
    __nv_bfloat16 h0 = __float2bfloat16(v.x), h1 = __float2bfloat16(v.y);
    __nv_bfloat16 h2 = __float2bfloat16(v.z), h3 = __float2bfloat16(v.w);
    __nv_bfloat162 hA = {h0, h1}, hB = {h2, h3};
    __nv_bfloat162 lA = {__float2bfloat16(v.x - __bfloat162float(h0)),
                         __float2bfloat16(v.y - __bfloat162float(h1))};
    __nv_bfloat162 lB = {__float2bfloat16(v.z - __bfloat162float(h2)),
                         __float2bfloat16(v.w - __bfloat162float(h3))};
    reinterpret_cast<__nv_bfloat162*>(hi)[i * 2]     = hA;
    reinterpret_cast<__nv_bfloat162*>(hi)[i * 2 + 1] = hB;
    reinterpret_cast<__nv_bfloat162*>(lo)[i * 2]     = lA;
    reinterpret_cast<__nv_bfloat162*>(lo)[i * 2 + 1] = lB;
}

// ---------------------------------------------------------------------------
// Transpose + split: in[b][r][c] (fp32) -> out[(outRowOff + b*Cc + c)][r] bf16 hi/lo
// ---------------------------------------------------------------------------
__global__ __launch_bounds__(256) void transpose_split(
    const float* __restrict__ in, __nv_bfloat16* __restrict__ ohi,
    __nv_bfloat16* __restrict__ olo, int Cc, long inBatch, long outRowOff, int outK)
{
    __shared__ float t[32][33];
    int b  = blockIdx.z;
    int r0 = blockIdx.y * 32, c0 = blockIdx.x * 32;
    int tx = threadIdx.x & 31, ty = threadIdx.x >> 5;
#pragma unroll
    for (int j = 0; j < 4; j++) {
        int r = r0 + ty + j * 8;
        t[ty + j * 8][tx] = in[(size_t)b * inBatch + (size_t)r * Cc + c0 + tx];
    }
    __syncthreads();
#pragma unroll
    for (int j = 0; j < 4; j++) {
        int cI = c0 + ty + j * 8;
        size_t orow = (size_t)outRowOff + (size_t)b * Cc + cI;
        int k = r0 + tx;
        float v = t[tx][ty + j * 8];
        __nv_bfloat16 h = __float2bfloat16(v);
        ohi[orow * outK + k] = h;
        olo[orow * outK + k] = __float2bfloat16(v - __bfloat162float(h));
    }
}

// ---------------------------------------------------------------------------
// mma.sync bf16 split GEMM: C[M,N] = A[M,K] * B[N,K]^T (3-term hi/lo)
// CTA 128x128, K-chunk 32, 8 warps (warp tile 64x32), double-buffered cp.async.
// ---------------------------------------------------------------------------
#define PITCH   40                 // bf16 per smem row (80 B) -> ldmatrix conflict-free
#define TILE_B  (128 * 80)         // 10240 B per tile
#define BUF_B   (4 * TILE_B)       // Ahi, Alo, Bhi, Blo
#define GEMM_SMEM (2 * BUF_B)      // 81920 B, double-buffered

template <bool BIAS, bool RELU, bool RES, bool OUTF, bool OUTB>
__global__ __launch_bounds__(256) void gemm_mma(
    const __nv_bfloat16* __restrict__ Ahi, const __nv_bfloat16* __restrict__ Alo,
    const __nv_bfloat16* __restrict__ Bhi, const __nv_bfloat16* __restrict__ Blo,
    const float* __restrict__ bias, const float* __restrict__ res,
    float* __restrict__ Cf, __nv_bfloat16* __restrict__ Chi,
    __nv_bfloat16* __restrict__ Clo, int M, int N, int K)
{
    extern __shared__ char smem[];
    const uint32_t sb = smem_u32(smem);
    const int tid = threadIdx.x;
    const int lane = tid & 31, wid = tid >> 5;
    const int rowBase = blockIdx.y * 128;
    const int colBase = blockIdx.x * 128;

    // ---- load mapping: 2 iterations x 4 tiles x 16B per thread ----
    const int lr = tid >> 2;        // 0..63
    const int ls = tid & 3;         // 16B segment within 64B row

    auto issue = [&](int c) {
        const int k0 = c << 5;
        const uint32_t buf = sb + (c & 1) * BUF_B;
#pragma unroll
        for (int i = 0; i < 2; i++) {
            int r = lr + i * 64;
            uint32_t so = (uint32_t)r * 80 + ls * 16;
            size_t gaA = (size_t)(rowBase + r) * K + k0 + ls * 8;
            size_t gaB = (size_t)(colBase + r) * K + k0 + ls * 8;
            cp_async16(buf + so,              Ahi + gaA);
            cp_async16(buf + TILE_B + so,     Alo + gaA);
            cp_async16(buf + 2 * TILE_B + so, Bhi + gaB);
            cp_async16(buf + 3 * TILE_B + so, Blo + gaB);
        }
        CP_COMMIT();
    };

    // ---- mma fragment addressing ----
    const int wm = wid >> 2, wn = wid & 3;     // warp 2x4 grid
    const int t8 = lane >> 3, r8 = lane & 7;
    const int aR = r8 + ((t8 & 1) << 3);       // A ldmatrix x4 row
    const int aK = (t8 & 2) << 2;              // 0 or 8
    const int bR = r8 + ((t8 >> 1) << 3);      // B ldmatrix x4 row
    const int bK = (t8 & 1) << 3;              // 0 or 8

    float acc[4][4][4];
#pragma unroll
    for (int i = 0; i < 4; i++)
#pragma unroll
        for (int j = 0; j < 4; j++)
#pragma unroll
            for (int q = 0; q < 4; q++) acc[i][j][q] = 0.0f;

    const int nch = K >> 5;
    issue(0);

    for (int c = 0; c < nch; c++) {
        if (c + 1 < nch) { issue(c + 1); CP_WAIT(1); }
        else             { CP_WAIT(0); }
        __syncthreads();

        const uint32_t buf = sb + (c & 1) * BUF_B;
        const uint32_t aBase  = buf + (uint32_t)(wm * 64 + aR) * 80 + aK * 2;
        const uint32_t alBase = aBase + TILE_B;
        const uint32_t bBase  = buf + 2 * TILE_B + (uint32_t)(wn * 32 + bR) * 80 + bK * 2;
        const uint32_t blBase = bBase + TILE_B;

#pragma unroll
        for (int ks = 0; ks < 2; ks++) {
            const uint32_t ko = ks * 32;   // 16 bf16 = 32 bytes
            uint32_t ah[4][4], al[4][4], bh[2][4], bl[2][4];
#pragma unroll
            for (int mt = 0; mt < 4; mt++) {
                ldsm_x4(ah[mt], aBase  + (uint32_t)mt * 16 * 80 + ko);
                ldsm_x4(al[mt], alBase + (uint32_t)mt * 16 * 80 + ko);
            }
#pragma unroll
            for (int j = 0; j < 2; j++) {
                ldsm_x4(bh[j], bBase  + (uint32_t)j * 16 * 80 + ko);
                ldsm_x4(bl[j], blBase + (uint32_t)j * 16 * 80 + ko);
            }
#pragma unroll
            for (int mt = 0; mt < 4; mt++) {
#pragma unroll
                for (int nt = 0; nt < 4; nt++) {
                    const uint32_t* bhp = &bh[nt >> 1][(nt & 1) * 2];
                    const uint32_t* blp = &bl[nt >> 1][(nt & 1) * 2];
                    mma_bf16(acc[mt][nt], ah[mt], bhp);
                    mma_bf16(acc[mt][nt], ah[mt], blp);
                    mma_bf16(acc[mt][nt], al[mt], bhp);
                }
            }
        }
        __syncthreads();
    }

    // ---- epilogue: registers -> global (fp32 / bf16 hi+lo) ----
    const int lrr = lane >> 2, lcc = (lane & 3) * 2;
#pragma unroll
    for (int mt = 0; mt < 4; mt++) {
#pragma unroll
        for (int half = 0; half < 2; half++) {
            const int row = rowBase + wm * 64 + mt * 16 + lrr + half * 8;
#pragma unroll
            for (int nt = 0; nt < 4; nt++) {
                const int col = colBase + wn * 32 + nt * 8 + lcc;
                float v0 = acc[mt][nt][half * 2];
                float v1 = acc[mt][nt][half * 2 + 1];
                if (BIAS) { v0 += bias[col]; v1 += bias[col + 1]; }
                if (RES) {
                    const float2 r2 = *reinterpret_cast<const float2*>(
                        &res[(size_t)row * N + col]);
                    v0 += r2.x; v1 += r2.y;
                }
                if (RELU) { v0 = fmaxf(v0, 0.f); v1 = fmaxf(v1, 0.f); }
                const size_t o = (size_t)row * N + col;
                if (OUTF) {
                    float2 w = {v0, v1};
                    *reinterpret_cast<float2*>(&Cf[o]) = w;
                }
                if (OUTB) {
                    __nv_bfloat16 h0 = __float2bfloat16(v0);
                    __nv_bfloat16 h1 = __float2bfloat16(v1);
                    __nv_bfloat162 hp = {h0, h1};
                    __nv_bfloat162 lp = {__float2bfloat16(v0 - __bfloat162float(h0)),
                                         __float2bfloat16(v1 - __bfloat162float(h1))};
                    *reinterpret_cast<__nv_bfloat162*>(&Chi[o]) = hp;
                    *reinterpret_cast<__nv_bfloat162*>(&Clo[o]) = lp;
                }
            }
        }
    }
}

// ---------------------------------------------------------------------------
// Flash-style causal attention (fp32). qkv packed [M][3072]; writes y hi/lo bf16.
// ---------------------------------------------------------------------------
__global__ __launch_bounds__(256) void attn_kernel(
    const float* __restrict__ qkv,
    __nv_bfloat16* __restrict__ yhi, __nv_bfloat16* __restrict__ ylo)
{
    __shared__ float Qst[64][65];
    __shared__ float Kst[64][33];
    __shared__ float Vs [32][65];
    __shared__ float Pst[32][65];

    const int tid = threadIdx.x;
    const int tx = tid & 15;
    const int ty = tid >> 4;
    const int bh = blockIdx.y;
    const int b  = bh >> 4;
    const int h  = bh & 15;
    const int t0 = blockIdx.x * 64;
    const float scale = 0.03125f;

    const size_t rb = ((size_t)b * TT) * 3072 + h * 64;

    {
        int d = tid & 63, r0 = tid >> 6;
#pragma unroll
        for (int r = r0; r < 64; r += 4)
            Qst[d][r] = qkv[rb + (size_t)(t0 + r) * 3072 + d] * scale;
    }

    float m_i[4], l_i[4], acc[4][4];
#pragma unroll
    for (int i = 0; i < 4; i++) {
        m_i[i] = -1e30f; l_i[i] = 0.0f;
#pragma unroll
        for (int j = 0; j < 4; j++) acc[i][j] = 0.0f;
    }

    const int ntiles = t0 / 32 + 2;
    for (int it = 0; it < ntiles; it++) {
        const int s0 = it * 32;
        __syncthreads();
        {
            int d = tid & 63, sc0 = tid >> 6;
#pragma unroll
            for (int sc = sc0; sc < 32; sc += 4) {
                Kst[d][sc] = qkv[rb + 1024 + (size_t)(s0 + sc) * 3072 + d];
                Vs[sc][d]  = qkv[rb + 2048 + (size_t)(s0 + sc) * 3072 + d];
            }
        }
        __syncthreads();

        float s[4][2];
#pragma unroll
        for (int i = 0; i < 4; i++) { s[i][0] = 0.0f; s[i][1] = 0.0f; }
#pragma unroll 8
        for (int d = 0; d < 64; d++) {
            float qa0 = Qst[d][ty * 4 + 0];
            float qa1 = Qst[d][ty * 4 + 1];
            float qa2 = Qst[d][ty * 4 + 2];
            float qa3 = Qst[d][ty * 4 + 3];
            float kb0 = Kst[d][tx * 2 + 0];
            float kb1 = Kst[d][tx * 2 + 1];
            s[0][0] = fmaf(qa0, kb0, s[0][0]); s[0][1] = fmaf(qa0, kb1, s[0][1]);
            s[1][0] = fmaf(qa1, kb0, s[1][0]); s[1][1] = fmaf(qa1, kb1, s[1][1]);
            s[2][0] = fmaf(qa2, kb0, s[2][0]); s[2][1] = fmaf(qa2, kb1, s[2][1]);
            s[3][0] = fmaf(qa3, kb0, s[3][0]); s[3][1] = fmaf(qa3, kb1, s[3][1]);
        }

        if (s0 + 31 > t0) {
#pragma unroll
            for (int i = 0; i < 4; i++)
#pragma unroll
                for (int j = 0; j < 2; j++)
                    if (s0 + tx * 2 + j > t0 + ty * 4 + i) s[i][j] = -1e30f;
        }

        float alpha[4];
#pragma unroll
        for (int i = 0; i < 4; i++) {
            float tm = fmaxf(s[i][0], s[i][1]);
            tm = fmaxf(tm, __shfl_xor_sync(0xffffffffu, tm, 1));
            tm = fmaxf(tm, __shfl_xor_sync(0xffffffffu, tm, 2));
            tm = fmaxf(tm, __shfl_xor_sync(0xffffffffu, tm, 4));
            tm = fmaxf(tm, __shfl_xor_sync(0xffffffffu, tm, 8));
            float mn = fmaxf(m_i[i], tm);
            alpha[i] = __expf(m_i[i] - mn);
            m_i[i] = mn;
            float p0 = __expf(s[i][0] - mn);
            float p1 = __expf(s[i][1] - mn);
            s[i][0] = p0; s[i][1] = p1;
            float rs = p0 + p1;
            rs += __shfl_xor_sync(0xffffffffu, rs, 1);
            rs += __shfl_xor_sync(0xffffffffu, rs, 2);
            rs += __shfl_xor_sync(0xffffffffu, rs, 4);
            rs += __shfl_xor_sync(0xffffffffu, rs, 8);
            l_i[i] = l_i[i] * alpha[i] + rs;
        }
#pragma unroll
        for (int i = 0; i < 4; i++)
#pragma unroll
            for (int j = 0; j < 4; j++) acc[i][j] *= alpha[i];

#pragma unroll
        for (int i = 0; i < 4; i++)
#pragma unroll
            for (int j = 0; j < 2; j++)
                Pst[tx * 2 + j][ty * 4 + i] = s[i][j];
        __syncthreads();

#pragma unroll 4
        for (int ss = 0; ss < 32; ss++) {
            float pa0 = Pst[ss][ty * 4 + 0];
            float pa1 = Pst[ss][ty * 4 + 1];
            float pa2 = Pst[ss][ty * 4 + 2];
            float pa3 = Pst[ss][ty * 4 + 3];
            float vb0 = Vs[ss][tx * 4 + 0];
            float vb1 = Vs[ss][tx * 4 + 1];
            float vb2 = Vs[ss][tx * 4 + 2];
            float vb3 = Vs[ss][tx * 4 + 3];
            acc[0][0] = fmaf(pa0, vb0, acc[0][0]); acc[0][1] = fmaf(pa0, vb1, acc[0][1]);
            acc[0][2] = fmaf(pa0, vb2, acc[0][2]); acc[0][3] = fmaf(pa0, vb3, acc[0][3]);
            acc[1][0] = fmaf(pa1, vb0, acc[1][0]); acc[1][1] = fmaf(pa1, vb1, acc[1][1]);
            acc[1][2] = fmaf(pa1, vb2, acc[1][2]); acc[1][3] = fmaf(pa1, vb3, acc[1][3]);
            acc[2][0] = fmaf(pa2, vb0, acc[2][0]); acc[2][1] = fmaf(pa2, vb1, acc[2][1]);
            acc[2][2] = fmaf(pa2, vb2, acc[2][2]); acc[2][3] = fmaf(pa2, vb3, acc[2][3]);
            acc[3][0] = fmaf(pa3, vb0, acc[3][0]); acc[3][1] = fmaf(pa3, vb1, acc[3][1]);
            acc[3][2] = fmaf(pa3, vb2, acc[3][2]); acc[3][3] = fmaf(pa3, vb3, acc[3][3]);
        }
    }

    const size_t yb = ((size_t)b * TT) * CC + h * 64;
#pragma unroll
    for (int i = 0; i < 4; i++) {
        float inv = 1.0f / l_i[i];
        int t = t0 + ty * 4 + i;
        size_t o = yb + (size_t)t * CC + tx * 4;
#pragma unroll
        for (int j = 0; j < 4; j++) {
            float v = acc[i][j] * inv;
            __nv_bfloat16 hh = __float2bfloat16(v);
            yhi[o + j] = hh;
            ylo[o + j] = __float2bfloat16(v - __bfloat162float(hh));
        }
    }
}

// ---------------------------------------------------------------------------
// Launch sequence
// ---------------------------------------------------------------------------
extern "C" void kernel_launch(void* const* d_in, const int* in_sizes, int n_in,
                              void* d_out, int out_size)
{
    const float* x     = (const float*)d_in[0];
    const float* Wq    = (const float*)d_in[1];
    const float* Wk    = (const float*)d_in[2];
    const float* Wv    = (const float*)d_in[3];
    const float* Wproj = (const float*)d_in[4];
    const float* bproj = (const float*)d_in[5];
    const float* W1    = (const float*)d_in[6];
    const float* b1    = (const float*)d_in[7];
    const float* W2    = (const float*)d_in[8];
    const float* b2    = (const float*)d_in[9];
    float* out = (float*)d_out;

    __nv_bfloat16 *xhi, *xlo, *Bqh, *Bql, *Bph, *Bpl, *B1h, *B1l, *B2h, *B2l;
    __nv_bfloat16 *yhi, *ylo, *x2h, *x2l, *h1h, *h1l;
    float *qkv, *x2;
    cudaGetSymbolAddress((void**)&xhi, g_xhi);   cudaGetSymbolAddress((void**)&xlo, g_xlo);
    cudaGetSymbolAddress((void**)&Bqh, g_Bqkv_hi); cudaGetSymbolAddress((void**)&Bql, g_Bqkv_lo);
    cudaGetSymbolAddress((void**)&Bph, g_Bp_hi); cudaGetSymbolAddress((void**)&Bpl, g_Bp_lo);
    cudaGetSymbolAddress((void**)&B1h, g_B1_hi); cudaGetSymbolAddress((void**)&B1l, g_B1_lo);
    cudaGetSymbolAddress((void**)&B2h, g_B2_hi); cudaGetSymbolAddress((void**)&B2l, g_B2_lo);
    cudaGetSymbolAddress((void**)&qkv, g_qkv);
    cudaGetSymbolAddress((void**)&yhi, g_yhi);   cudaGetSymbolAddress((void**)&ylo, g_ylo);
    cudaGetSymbolAddress((void**)&x2,  g_x2);
    cudaGetSymbolAddress((void**)&x2h, g_x2hi);  cudaGetSymbolAddress((void**)&x2l, g_x2lo);
    cudaGetSymbolAddress((void**)&h1h, g_h1hi);  cudaGetSymbolAddress((void**)&h1l, g_h1lo);

    cudaFuncSetAttribute(gemm_mma<false,false,false,true,false>,
                         cudaFuncAttributeMaxDynamicSharedMemorySize, GEMM_SMEM);
    cudaFuncSetAttribute(gemm_mma<true,false,true,true,true>,
                         cudaFuncAttributeMaxDynamicSharedMemorySize, GEMM_SMEM);
    cudaFuncSetAttribute(gemm_mma<true,true,false,false,true>,
                         cudaFuncAttributeMaxDynamicSharedMemorySize, GEMM_SMEM);
    cudaFuncSetAttribute(gemm_mma<true,false,true,true,false>,
                         cudaFuncAttributeMaxDynamicSharedMemorySize, GEMM_SMEM);

    dim3 tpb(256);

    // Prepass: input split + weight transposes
    conv_split<<<(MROWS * CC / 4 + 255) / 256, tpb>>>(x, xhi, xlo, MROWS * CC / 4);
    transpose_split<<<dim3(2, 32, 16), tpb>>>(Wq, Bqh, Bql, 64, (long)CC * 64, 0,    CC);
    transpose_split<<<dim3(2, 32, 16), tpb>>>(Wk, Bqh, Bql, 64, (long)CC * 64, 1024, CC);
    transpose_split<<<dim3(2, 32, 16), tpb>>>(Wv, Bqh, Bql, 64, (long)CC * 64, 2048, CC);
    transpose_split<<<dim3(32, 32, 1), tpb>>>(Wproj, Bph, Bpl, CC, 0, 0, CC);
    transpose_split<<<dim3(128, 32, 1), tpb>>>(W1, B1h, B1l, FF, 0, 0, CC);
    transpose_split<<<dim3(32, 128, 1), tpb>>>(W2, B2h, B2l, CC, 0, 0, FF);

    // Fused QKV: [8192,1024] @ [3072,1024]^T -> qkv fp32
    gemm_mma<false,false,false,true,false><<<dim3(3072 / 128, MROWS / 128), tpb, GEMM_SMEM>>>(
        xhi, xlo, Bqh, Bql, nullptr, nullptr, qkv, nullptr, nullptr, MROWS, 3072, CC);

    // Causal attention -> y (bf16 hi/lo)
    attn_kernel<<<dim3(TT / 64, BB * HH), tpb>>>(qkv, yhi, ylo);

    // Output projection + bias + residual(x) -> x2 fp32 + hi/lo
    gemm_mma<true,false,true,true,true><<<dim3(CC / 128, MROWS / 128), tpb, GEMM_SMEM>>>(
        yhi, ylo, Bph, Bpl, bproj, x, x2, x2h, x2l, MROWS, CC, CC);

    // FF1: relu(x2 @ W1 + b1) -> h1 hi/lo
    gemm_mma<true,true,false,false,true><<<dim3(FF / 128, MROWS / 128), tpb, GEMM_SMEM>>>(
        x2h, x2l, B1h, B1l, b1, nullptr, nullptr, h1h, h1l, MROWS, FF, CC);

    // FF2: h1 @ W2 + b2 + x2 -> out fp32
    gemm_mma<true,false,true,true,false><<<dim3(CC / 128, MROWS / 128), tpb, GEMM_SMEM>>>(
        h1h, h1l, B2h, B2l, b2, x2, out, nullptr, nullptr, MROWS, CC, FF);
}

// round 4
// speedup vs baseline: 2.6145x; 1.4966x over previous
#include <cuda_runtime.h>
#include <cuda_fp16.h>
#include <cstdint>

// Problem constants
#define BB 4
#define TT 2048
#define CC 1024
#define FF 4096
#define MROWS 8192

// ---------------------------------------------------------------------------
// PTX helpers (sm_103 base ISA: cp.async, ldmatrix, mma.sync)
// ---------------------------------------------------------------------------
__device__ __forceinline__ uint32_t smem_u32(const void* p) {
    uint32_t a;
    asm("{ .reg .u64 t; cvta.to.shared.u64 t, %1; cvt.u32.u64 %0, t; }" : "=r"(a) : "l"(p));
    return a;
}
__device__ __forceinline__ void cp_async16(uint32_t s, const void* g) {
    asm volatile("cp.async.cg.shared.global [%0], [%1], 16;" :: "r"(s), "l"(g) : "memory");
}
#define CP_COMMIT() asm volatile("cp.async.commit_group;" ::: "memory")
#define CP_WAIT(n)  asm volatile("cp.async.wait_group %0;" :: "n"(n) : "memory")

__device__ __forceinline__ void ldsm_x4(uint32_t* r, uint32_t addr) {
    asm volatile("ldmatrix.sync.aligned.m8n8.x4.shared.b16 {%0,%1,%2,%3}, [%4];"
                 : "=r"(r[0]), "=r"(r[1]), "=r"(r[2]), "=r"(r[3]) : "r"(addr));
}
__device__ __forceinline__ void ldsm_x4_t(uint32_t* r, uint32_t addr) {
    asm volatile("ldmatrix.sync.aligned.m8n8.x4.trans.shared.b16 {%0,%1,%2,%3}, [%4];"
                 : "=r"(r[0]), "=r"(r[1]), "=r"(r[2]), "=r"(r[3]) : "r"(addr));
}
__device__ __forceinline__ void mma_f16(float* c, const uint32_t* a, const uint32_t* b) {
    asm volatile(
        "mma.sync.aligned.m16n8k16.row.col.f32.f16.f16.f32 "
        "{%0,%1,%2,%3}, {%4,%5,%6,%7}, {%8,%9}, {%0,%1,%2,%3};"
        : "+f"(c[0]), "+f"(c[1]), "+f"(c[2]), "+f"(c[3])
        : "r"(a[0]), "r"(a[1]), "r"(a[2]), "r"(a[3]), "r"(b[0]), "r"(b[1]));
}
__device__ __forceinline__ uint32_t pack_h2(float a, float b) {
    __half2 h = __floats2half2_rn(a, b);
    return reinterpret_cast<uint32_t&>(h);
}

// ---------------------------------------------------------------------------
// Scratch (device globals)
// ---------------------------------------------------------------------------
__device__ __half g_xh[MROWS * CC],  g_xl[MROWS * CC];
__device__ __half g_Bqkv[3072 * CC];
__device__ __half g_Bp[CC * CC], g_B1[FF * CC], g_B2[CC * FF];
__device__ __half g_qh[MROWS * 3072], g_ql[MROWS * 3072];
__device__ __half g_yh[MROWS * CC],  g_yl[MROWS * CC];
__device__ float  g_x2[MROWS * CC];
__device__ __half g_x2h[MROWS * CC], g_x2l[MROWS * CC];
__device__ __half g_h1h[MROWS * FF], g_h1l[MROWS * FF];

// ---------------------------------------------------------------------------
// fp32 -> fp16 hi/lo split (elementwise)
// ---------------------------------------------------------------------------
__global__ __launch_bounds__(256) void conv_split(
    const float* __restrict__ in, __half* __restrict__ hi,
    __half* __restrict__ lo, int n4)
{
    int i = blockIdx.x * 256 + threadIdx.x;
    if (i >= n4) return;
    float4 v = reinterpret_cast<const float4*>(in)[i];
    __half h0 = __float2half_rn(v.x), h1 = __float2half_rn(v.y);
    __half h2 = __float2half_rn(v.z), h3 = __float2half_rn(v.w);
    __half2 hA = {h0, h1}, hB = {h2, h3};
    __half2 lA = {__float2half_rn(v.x - __half2float(h0)),
                  __float2half_rn(v.y - __half2float(h1))};
    __half2 lB = {__float2half_rn(v.z - __half2float(h2)),
                  __float2half_rn(v.w - __half2float(h3))};
    reinterpret_cast<__half2*>(hi)[i * 2]     = hA;
    reinterpret_cast<__half2*>(hi)[i * 2 + 1] = hB;
    reinterpret_cast<__half2*>(lo)[i * 2]     = lA;
    reinterpret_cast<__half2*>(lo)[i * 2 + 1] = lB;
}

// ---------------------------------------------------------------------------
// Transpose (weights, hi-only): in[b][r][c] fp32 -> out[(off + b*Cc + c)][r] fp16
// ---------------------------------------------------------------------------
__global__ __launch_bounds__(256) void transpose_half(
    const float* __restrict__ in, __half* __restrict__ oh,
    int Cc, long inBatch, long outRowOff, int outK)
{
    __shared__ float t[32][33];
    int b  = blockIdx.z;
    int r0 = blockIdx.y * 32, c0 = blockIdx.x * 32;
    int tx = threadIdx.x & 31, ty = threadIdx.x >> 5;
#pragma unroll
    for (int j = 0; j < 4; j++) {
        int r = r0 + ty + j * 8;
        t[ty + j * 8][tx] = in[(size_t)b * inBatch + (size_t)r * Cc + c0 + tx];
    }
    __syncthreads();
#pragma unroll
    for (int j = 0; j < 4; j++) {
        int cI = c0 + ty + j * 8;
        size_t orow = (size_t)outRowOff + (size_t)b * Cc + cI;
        oh[orow * outK + r0 + tx] = __float2half_rn(t[tx][ty + j * 8]);
    }
}

// ---------------------------------------------------------------------------
// fp16 A-split GEMM: C[M,N] = (Ah+Al)[M,K] * B[N,K]^T,  2 MMAs per tile-step.
// CTA 128x128, K-chunk 32, 8 warps, 3-stage cp.async pipeline.
// ---------------------------------------------------------------------------
#define TILE_B   (128 * 80)         // 128 rows x 80B (pitch 40 halves)
#define CHUNK_B  (3 * TILE_B)       // Ah, Al, B
#define GEMM_SMEM (3 * CHUNK_B)     // 3 stages = 92160 B

template <bool BIAS, bool RELU, bool RES, bool OUTF, bool OUTH>
__global__ __launch_bounds__(256) void gemm_mma(
    const __half* __restrict__ Ah_, const __half* __restrict__ Al_,
    const __half* __restrict__ B_,
    const float* __restrict__ bias, const float* __restrict__ res,
    float* __restrict__ Cf, __half* __restrict__ Ch, __half* __restrict__ Cl,
    int M, int N, int K)
{
    extern __shared__ char smem[];
    const uint32_t sb = smem_u32(smem);
    const int tid = threadIdx.x;
    const int lane = tid & 31, wid = tid >> 5;
    const int rowBase = blockIdx.y * 128;
    const int colBase = blockIdx.x * 128;
    const int lr = tid >> 2, ls = tid & 3;

    auto issue = [&](int c) {
        const int k0 = c << 5;
        const uint32_t buf = sb + (uint32_t)(c % 3) * CHUNK_B;
#pragma unroll
        for (int i = 0; i < 2; i++) {
            int r = lr + i * 64;
            uint32_t so = (uint32_t)r * 80 + ls * 16;
            size_t gA = (size_t)(rowBase + r) * K + k0 + ls * 8;
            size_t gB = (size_t)(colBase + r) * K + k0 + ls * 8;
            cp_async16(buf + so,              Ah_ + gA);
            cp_async16(buf + TILE_B + so,     Al_ + gA);
            cp_async16(buf + 2 * TILE_B + so, B_  + gB);
        }
        CP_COMMIT();
    };

    const int wm = wid >> 2, wn = wid & 3;
    const int t8 = lane >> 3, r8 = lane & 7;
    const int aR = r8 + ((t8 & 1) << 3);
    const int aK = (t8 & 2) << 2;
    const int bR = r8 + ((t8 >> 1) << 3);
    const int bK = (t8 & 1) << 3;

    float acc[4][4][4];
#pragma unroll
    for (int i = 0; i < 4; i++)
#pragma unroll
        for (int j = 0; j < 4; j++)
#pragma unroll
            for (int q = 0; q < 4; q++) acc[i][j][q] = 0.0f;

    const int nch = K >> 5;
    issue(0); issue(1);

    for (int c = 0; c < nch; c++) {
        if (c + 1 < nch) { CP_WAIT(1); } else { CP_WAIT(0); }
        __syncthreads();
        if (c + 2 < nch) issue(c + 2);

        const uint32_t buf = sb + (uint32_t)(c % 3) * CHUNK_B;
        const uint32_t aB  = buf + (uint32_t)(wm * 64 + aR) * 80 + aK * 2;
        const uint32_t alB = aB + TILE_B;
        const uint32_t bB  = buf + 2 * TILE_B + (uint32_t)(wn * 32 + bR) * 80 + bK * 2;

#pragma unroll
        for (int ks = 0; ks < 2; ks++) {
            const uint32_t ko = ks * 32;
            uint32_t ah[4][4], al[4][4], bb[2][4];
#pragma unroll
            for (int mt = 0; mt < 4; mt++) {
                ldsm_x4(ah[mt], aB  + (uint32_t)mt * 16 * 80 + ko);
                ldsm_x4(al[mt], alB + (uint32_t)mt * 16 * 80 + ko);
            }
#pragma unroll
            for (int j = 0; j < 2; j++)
                ldsm_x4(bb[j], bB + (uint32_t)j * 16 * 80 + ko);
#pragma unroll
            for (int mt = 0; mt < 4; mt++) {
#pragma unroll
                for (int nt = 0; nt < 4; nt++) {
                    const uint32_t* bp = &bb[nt >> 1][(nt & 1) * 2];
                    mma_f16(acc[mt][nt], ah[mt], bp);
                    mma_f16(acc[mt][nt], al[mt], bp);
                }
            }
        }
    }

    // ---- epilogue ----
    const int lrr = lane >> 2, lcc = (lane & 3) * 2;
#pragma unroll
    for (int mt = 0; mt < 4; mt++) {
#pragma unroll
        for (int half = 0; half < 2; half++) {
            const int row = rowBase + wm * 64 + mt * 16 + lrr + half * 8;
#pragma unroll
            for (int nt = 0; nt < 4; nt++) {
                const int col = colBase + wn * 32 + nt * 8 + lcc;
                float v0 = acc[mt][nt][half * 2];
                float v1 = acc[mt][nt][half * 2 + 1];
                if (BIAS) { v0 += bias[col]; v1 += bias[col + 1]; }
                if (RES) {
                    const float2 r2 = *reinterpret_cast<const float2*>(
                        &res[(size_t)row * N + col]);
                    v0 += r2.x; v1 += r2.y;
                }
                if (RELU) { v0 = fmaxf(v0, 0.f); v1 = fmaxf(v1, 0.f); }
                const size_t o = (size_t)row * N + col;
                if (OUTF) {
                    float2 w = {v0, v1};
                    *reinterpret_cast<float2*>(&Cf[o]) = w;
                }
                if (OUTH) {
                    __half h0 = __float2half_rn(v0), h1 = __float2half_rn(v1);
                    __half2 hp = {h0, h1};
                    __half2 lp = {__float2half_rn(v0 - __half2float(h0)),
                                  __float2half_rn(v1 - __half2float(h1))};
                    *reinterpret_cast<__half2*>(&Ch[o]) = hp;
                    *reinterpret_cast<__half2*>(&Cl[o]) = lp;
                }
            }
        }
    }
}

// ---------------------------------------------------------------------------
// fp16 mma flash attention, causal. qh/ql: [M][3072] (q|k|v packed).
// CTA: 64 queries, 4 warps (16 rows each); key tiles of 64, double-buffered.
// Q split hi/lo for scores; K, V, P single fp16. Softmax fp32 in registers.
// ---------------------------------------------------------------------------
#define AQH 0
#define AQL 9216
#define AKV 18432                    // K buffers at 18432 + pb*9216
#define AVV 36864                    // V buffers at 36864 + pb*9216
#define ATTN_SMEM 55296              // 144B pitch x 64 rows x 6 tiles

__global__ __launch_bounds__(128) void attn_mma(
    const __half* __restrict__ qh, const __half* __restrict__ ql,
    __half* __restrict__ yh, __half* __restrict__ yl)
{
    extern __shared__ char smem[];
    const uint32_t sb = smem_u32(smem);
    const int tid = threadIdx.x, lane = tid & 31, w = tid >> 5;
    const int bhh = blockIdx.y, b = bhh >> 4, h = bhh & 15;
    const int t0 = blockIdx.x * 64;
    const int last = blockIdx.x;               // diagonal tile index
    const size_t rbase = ((size_t)b * TT) * 3072 + h * 64;

    const int ldr = tid >> 1;                  // 0..63 row
    const int ldsg = (tid & 1) * 4;            // segment group

    // Q hi/lo -> smem (group 0)
#pragma unroll
    for (int j = 0; j < 4; j++) {
        size_t g = rbase + (size_t)(t0 + ldr) * 3072 + (ldsg + j) * 8;
        uint32_t so = (uint32_t)ldr * 144 + (ldsg + j) * 16;
        cp_async16(sb + AQH + so, qh + g);
        cp_async16(sb + AQL + so, ql + g);
    }
    CP_COMMIT();

    auto issueKV = [&](int it) {
        const int s0 = it * 64;
        const uint32_t pb = (uint32_t)(it & 1) * 9216;
#pragma unroll
        for (int j = 0; j < 4; j++) {
            size_t gk = rbase + 1024 + (size_t)(s0 + ldr) * 3072 + (ldsg + j) * 8;
            uint32_t so = (uint32_t)ldr * 144 + (ldsg + j) * 16;
            cp_async16(sb + AKV + pb + so, qh + gk);
            cp_async16(sb + AVV + pb + so, qh + gk + 1024);
        }
        CP_COMMIT();
    };

    issueKV(0);                                 // group 1
    CP_WAIT(1);                                 // Q ready
    __syncthreads();

    // Q fragments (held for whole kernel)
    const int t8 = lane >> 3, r8 = lane & 7;
    const int aR = r8 + ((t8 & 1) << 3);
    const int aK = (t8 & 2) << 2;
    const int bR = r8 + ((t8 >> 1) << 3);
    const int bK = (t8 & 1) << 3;

    uint32_t qfh[4][4], qfl[4][4];
#pragma unroll
    for (int kd = 0; kd < 4; kd++) {
        uint32_t off = (uint32_t)(w * 16 + aR) * 144 + (kd * 16 + aK) * 2;
        ldsm_x4(qfh[kd], sb + AQH + off);
        ldsm_x4(qfl[kd], sb + AQL + off);
    }

    float m[2] = {-1e30f, -1e30f}, l[2] = {0.f, 0.f};
    float O[8][4];
#pragma unroll
    for (int i = 0; i < 8; i++)
#pragma unroll
        for (int j = 0; j < 4; j++) O[i][j] = 0.f;

    const int qr0 = w * 16 + (lane >> 2);       // local query row (and +8)

    for (int it = 0; it <= last; it++) {
        if (it < last) { issueKV(it + 1); CP_WAIT(1); } else { CP_WAIT(0); }
        __syncthreads();
        const uint32_t pb = (uint32_t)(it & 1) * 9216;

        // S = Q K^T (64x64 per warp-row-block: 8 n-tiles)
        float s[8][4];
#pragma unroll
        for (int i = 0; i < 8; i++)
#pragma unroll
            for (int j = 0; j < 4; j++) s[i][j] = 0.f;

#pragma unroll
        for (int kd = 0; kd < 4; kd++) {
            uint32_t kb[4][4];
#pragma unroll
            for (int g = 0; g < 4; g++)
                ldsm_x4(kb[g], sb + AKV + pb +
                        (uint32_t)(g * 16 + bR) * 144 + (kd * 16 + bK) * 2);
#pragma unroll
            for (int g = 0; g < 4; g++) {
                mma_f16(s[2 * g],     qfh[kd], &kb[g][0]);
                mma_f16(s[2 * g],     qfl[kd], &kb[g][0]);
                mma_f16(s[2 * g + 1], qfh[kd], &kb[g][2]);
                mma_f16(s[2 * g + 1], qfl[kd], &kb[g][2]);
            }
        }

        // scale + causal mask (diagonal tile only)
#pragma unroll
        for (int nt = 0; nt < 8; nt++)
#pragma unroll
            for (int e = 0; e < 4; e++) s[nt][e] *= 0.03125f;
        if (it == last) {
#pragma unroll
            for (int nt = 0; nt < 8; nt++)
#pragma unroll
                for (int e = 0; e < 4; e++) {
                    int kc = nt * 8 + (lane & 3) * 2 + (e & 1);
                    int qr = qr0 + (e >> 1) * 8;
                    if (kc > qr) s[nt][e] = -1e30f;
                }
        }

        // online softmax
        float mn[2] = {m[0], m[1]};
#pragma unroll
        for (int nt = 0; nt < 8; nt++) {
            mn[0] = fmaxf(mn[0], fmaxf(s[nt][0], s[nt][1]));
            mn[1] = fmaxf(mn[1], fmaxf(s[nt][2], s[nt][3]));
        }
#pragma unroll
        for (int i = 0; i < 2; i++) {
            mn[i] = fmaxf(mn[i], __shfl_xor_sync(0xffffffffu, mn[i], 1));
            mn[i] = fmaxf(mn[i], __shfl_xor_sync(0xffffffffu, mn[i], 2));
        }
        float alpha[2];
#pragma unroll
        for (int i = 0; i < 2; i++) {
            alpha[i] = __expf(m[i] - mn[i]);
            m[i] = mn[i];
        }
        float rs[2] = {0.f, 0.f};
#pragma unroll
        for (int nt = 0; nt < 8; nt++) {
#pragma unroll
            for (int e = 0; e < 4; e++) {
                float p = __expf(s[nt][e] - m[e >> 1]);
                s[nt][e] = p;
                rs[e >> 1] += p;
            }
        }
#pragma unroll
        for (int i = 0; i < 2; i++) {
            rs[i] += __shfl_xor_sync(0xffffffffu, rs[i], 1);
            rs[i] += __shfl_xor_sync(0xffffffffu, rs[i], 2);
            l[i] = l[i] * alpha[i] + rs[i];
        }
#pragma unroll
        for (int nt = 0; nt < 8; nt++) {
            O[nt][0] *= alpha[0]; O[nt][1] *= alpha[0];
            O[nt][2] *= alpha[1]; O[nt][3] *= alpha[1];
        }

        // O += P V  (P packed from s-fragments; V via ldmatrix.trans)
#pragma unroll
        for (int kk = 0; kk < 4; kk++) {
            uint32_t pa[4];
            pa[0] = pack_h2(s[2 * kk][0],     s[2 * kk][1]);
            pa[1] = pack_h2(s[2 * kk][2],     s[2 * kk][3]);
            pa[2] = pack_h2(s[2 * kk + 1][0], s[2 * kk + 1][1]);
            pa[3] = pack_h2(s[2 * kk + 1][2], s[2 * kk + 1][3]);
#pragma unroll
            for (int dg = 0; dg < 4; dg++) {
                uint32_t vb[4];
                ldsm_x4_t(vb, sb + AVV + pb +
                          (uint32_t)(kk * 16 + aR) * 144 + (dg * 16 + aK) * 2);
                mma_f16(O[dg * 2],     pa, &vb[0]);
                mma_f16(O[dg * 2 + 1], pa, &vb[2]);
            }
        }
        __syncthreads();
    }

    // epilogue: normalize, split hi/lo fp16, store
    float inv[2] = {1.0f / l[0], 1.0f / l[1]};
    const size_t ob = ((size_t)b * TT) * CC + h * 64;
#pragma unroll
    for (int nt = 0; nt < 8; nt++) {
        int col = nt * 8 + (lane & 3) * 2;
#pragma unroll
        for (int i = 0; i < 2; i++) {
            int row = t0 + qr0 + i * 8;
            float v0 = O[nt][2 * i]     * inv[i];
            float v1 = O[nt][2 * i + 1] * inv[i];
            __half h0 = __float2half_rn(v0), h1 = __float2half_rn(v1);
            __half2 hp = {h0, h1};
            __half2 lp = {__float2half_rn(v0 - __half2float(h0)),
                          __float2half_rn(v1 - __half2float(h1))};
            size_t o = ob + (size_t)row * CC + col;
            *reinterpret_cast<__half2*>(&yh[o]) = hp;
            *reinterpret_cast<__half2*>(&yl[o]) = lp;
        }
    }
}

// ---------------------------------------------------------------------------
// Launch sequence
// ---------------------------------------------------------------------------
extern "C" void kernel_launch(void* const* d_in, const int* in_sizes, int n_in,
                              void* d_out, int out_size)
{
    const float* x     = (const float*)d_in[0];
    const float* Wq    = (const float*)d_in[1];
    const float* Wk    = (const float*)d_in[2];
    const float* Wv    = (const float*)d_in[3];
    const float* Wproj = (const float*)d_in[4];
    const float* bproj = (const float*)d_in[5];
    const float* W1    = (const float*)d_in[6];
    const float* b1    = (const float*)d_in[7];
    const float* W2    = (const float*)d_in[8];
    const float* b2    = (const float*)d_in[9];
    float* out = (float*)d_out;

    __half *xh, *xl, *Bqkv, *Bp, *B1, *B2, *qh, *ql, *yh, *yl, *x2h, *x2l, *h1h, *h1l;
    float *x2;
    cudaGetSymbolAddress((void**)&xh,  g_xh);   cudaGetSymbolAddress((void**)&xl,  g_xl);
    cudaGetSymbolAddress((void**)&Bqkv, g_Bqkv);
    cudaGetSymbolAddress((void**)&Bp,  g_Bp);
    cudaGetSymbolAddress((void**)&B1,  g_B1);   cudaGetSymbolAddress((void**)&B2,  g_B2);
    cudaGetSymbolAddress((void**)&qh,  g_qh);   cudaGetSymbolAddress((void**)&ql,  g_ql);
    cudaGetSymbolAddress((void**)&yh,  g_yh);   cudaGetSymbolAddress((void**)&yl,  g_yl);
    cudaGetSymbolAddress((void**)&x2,  g_x2);
    cudaGetSymbolAddress((void**)&x2h, g_x2h);  cudaGetSymbolAddress((void**)&x2l, g_x2l);
    cudaGetSymbolAddress((void**)&h1h, g_h1h);  cudaGetSymbolAddress((void**)&h1l, g_h1l);

    cudaFuncSetAttribute(gemm_mma<false,false,false,false,true>,
                         cudaFuncAttributeMaxDynamicSharedMemorySize, GEMM_SMEM);
    cudaFuncSetAttribute(gemm_mma<true,false,true,true,true>,
                         cudaFuncAttributeMaxDynamicSharedMemorySize, GEMM_SMEM);
    cudaFuncSetAttribute(gemm_mma<true,true,false,false,true>,
                         cudaFuncAttributeMaxDynamicSharedMemorySize, GEMM_SMEM);
    cudaFuncSetAttribute(gemm_mma<true,false,true,true,false>,
                         cudaFuncAttributeMaxDynamicSharedMemorySize, GEMM_SMEM);
    cudaFuncSetAttribute(attn_mma,
                         cudaFuncAttributeMaxDynamicSharedMemorySize, ATTN_SMEM);

    dim3 tpb(256);

    // Prepass: input split + weight transposes (weights hi only)
    conv_split<<<(MROWS * CC / 4 + 255) / 256, tpb>>>(x, xh, xl, MROWS * CC / 4);
    transpose_half<<<dim3(2, 32, 16), tpb>>>(Wq, Bqkv, 64, (long)CC * 64, 0,    CC);
    transpose_half<<<dim3(2, 32, 16), tpb>>>(Wk, Bqkv, 64, (long)CC * 64, 1024, CC);
    transpose_half<<<dim3(2, 32, 16), tpb>>>(Wv, Bqkv, 64, (long)CC * 64, 2048, CC);
    transpose_half<<<dim3(32, 32, 1), tpb>>>(Wproj, Bp, CC, 0, 0, CC);
    transpose_half<<<dim3(128, 32, 1), tpb>>>(W1, B1, FF, 0, 0, CC);
    transpose_half<<<dim3(32, 128, 1), tpb>>>(W2, B2, CC, 0, 0, FF);

    // Fused QKV -> qkv hi/lo fp16
    gemm_mma<false,false,false,false,true><<<dim3(3072 / 128, MROWS / 128), tpb, GEMM_SMEM>>>(
        xh, xl, Bqkv, nullptr, nullptr, nullptr, qh, ql, MROWS, 3072, CC);

    // Causal attention (tensor cores) -> y hi/lo fp16
    attn_mma<<<dim3(TT / 64, BB * 16), dim3(128), ATTN_SMEM>>>(qh, ql, yh, yl);

    // Output projection + bias + residual(x) -> x2 fp32 + hi/lo
    gemm_mma<true,false,true,true,true><<<dim3(CC / 128, MROWS / 128), tpb, GEMM_SMEM>>>(
        yh, yl, Bp, bproj, x, x2, x2h, x2l, MROWS, CC, CC);

    // FF1: relu(x2 @ W1 + b1) -> h1 hi/lo
    gemm_mma<true,true,false,false,true><<<dim3(FF / 128, MROWS / 128), tpb, GEMM_SMEM>>>(
        x2h, x2l, B1, b1, nullptr, nullptr, h1h, h1l, MROWS, FF, CC);

    // FF2: h1 @ W2 + b2 + x2 -> out fp32
    gemm_mma<true,false,true,true,false><<<dim3(CC / 128, MROWS / 128), tpb, GEMM_SMEM>>>(
        h1h, h1l, B2, b2, x2, out, nullptr, nullptr, MROWS, CC, FF);
}

// round 5
// speedup vs baseline: 6.4964x; 2.4847x over previous
#include <cuda_runtime.h>
#include <cuda_fp16.h>
#include <cstdint>

// Problem constants
#define BB 4
#define TT 2048
#define CC 1024
#define FF 4096
#define MROWS 8192

// ---------------------------------------------------------------------------
// PTX helpers (sm_103 base ISA: cp.async, ldmatrix, mma.sync)
// ---------------------------------------------------------------------------
__device__ __forceinline__ uint32_t smem_u32(const void* p) {
    uint32_t a;
    asm("{ .reg .u64 t; cvta.to.shared.u64 t, %1; cvt.u32.u64 %0, t; }" : "=r"(a) : "l"(p));
    return a;
}
__device__ __forceinline__ void cp_async16(uint32_t s, const void* g) {
    asm volatile("cp.async.cg.shared.global [%0], [%1], 16;" :: "r"(s), "l"(g) : "memory");
}
#define CP_COMMIT() asm volatile("cp.async.commit_group;" ::: "memory")
#define CP_WAIT(n)  asm volatile("cp.async.wait_group %0;" :: "n"(n) : "memory")

__device__ __forceinline__ void ldsm_x4(uint32_t* r, uint32_t addr) {
    asm volatile("ldmatrix.sync.aligned.m8n8.x4.shared.b16 {%0,%1,%2,%3}, [%4];"
                 : "=r"(r[0]), "=r"(r[1]), "=r"(r[2]), "=r"(r[3]) : "r"(addr));
}
__device__ __forceinline__ void ldsm_x4_t(uint32_t* r, uint32_t addr) {
    asm volatile("ldmatrix.sync.aligned.m8n8.x4.trans.shared.b16 {%0,%1,%2,%3}, [%4];"
                 : "=r"(r[0]), "=r"(r[1]), "=r"(r[2]), "=r"(r[3]) : "r"(addr));
}
__device__ __forceinline__ void mma_f16(float* c, const uint32_t* a, const uint32_t* b) {
    asm volatile(
        "mma.sync.aligned.m16n8k16.row.col.f32.f16.f16.f32 "
        "{%0,%1,%2,%3}, {%4,%5,%6,%7}, {%8,%9}, {%0,%1,%2,%3};"
        : "+f"(c[0]), "+f"(c[1]), "+f"(c[2]), "+f"(c[3])
        : "r"(a[0]), "r"(a[1]), "r"(a[2]), "r"(a[3]), "r"(b[0]), "r"(b[1]));
}
__device__ __forceinline__ uint32_t pack_h2(float a, float b) {
    __half2 h = __floats2half2_rn(a, b);
    return reinterpret_cast<uint32_t&>(h);
}

// ---------------------------------------------------------------------------
// Scratch (device globals) — all single fp16 now
// ---------------------------------------------------------------------------
__device__ __half g_xh[MROWS * CC];
__device__ __half g_Bqkv[3072 * CC];
__device__ __half g_Bp[CC * CC], g_B1[FF * CC], g_B2[CC * FF];
__device__ __half g_qkv[MROWS * 3072];
__device__ __half g_yh[MROWS * CC];
__device__ float  g_x2[MROWS * CC];
__device__ __half g_x2h[MROWS * CC];
__device__ __half g_h1h[MROWS * FF];

// ---------------------------------------------------------------------------
// fp32 -> fp16 (elementwise, float4)
// ---------------------------------------------------------------------------
__global__ __launch_bounds__(256) void conv_half(
    const float* __restrict__ in, __half* __restrict__ hi, int n4)
{
    int i = blockIdx.x * 256 + threadIdx.x;
    if (i >= n4) return;
    float4 v = reinterpret_cast<const float4*>(in)[i];
    __half2 hA = __floats2half2_rn(v.x, v.y);
    __half2 hB = __floats2half2_rn(v.z, v.w);
    reinterpret_cast<__half2*>(hi)[i * 2]     = hA;
    reinterpret_cast<__half2*>(hi)[i * 2 + 1] = hB;
}

// ---------------------------------------------------------------------------
// Transpose weights: in[b][r][c] fp32 -> out[(off + b*Cc + c)][r] fp16
// ---------------------------------------------------------------------------
__global__ __launch_bounds__(256) void transpose_half(
    const float* __restrict__ in, __half* __restrict__ oh,
    int Cc, long inBatch, long outRowOff, int outK)
{
    __shared__ float t[32][33];
    int b  = blockIdx.z;
    int r0 = blockIdx.y * 32, c0 = blockIdx.x * 32;
    int tx = threadIdx.x & 31, ty = threadIdx.x >> 5;
#pragma unroll
    for (int j = 0; j < 4; j++) {
        int r = r0 + ty + j * 8;
        t[ty + j * 8][tx] = in[(size_t)b * inBatch + (size_t)r * Cc + c0 + tx];
    }
    __syncthreads();
#pragma unroll
    for (int j = 0; j < 4; j++) {
        int cI = c0 + ty + j * 8;
        size_t orow = (size_t)outRowOff + (size_t)b * Cc + cI;
        oh[orow * outK + r0 + tx] = __float2half_rn(t[tx][ty + j * 8]);
    }
}

// ---------------------------------------------------------------------------
// fp16 GEMM: C[M,N] = A[M,K] * B[N,K]^T.  CTA 128x128, K-chunk 32, 8 warps,
// 3-stage cp.async pipeline, single MMA per tile-step.
// ---------------------------------------------------------------------------
#define TILE_B   (128 * 80)         // 128 rows x 80B (pitch 40 halves)
#define CHUNK_B  (2 * TILE_B)       // A, B
#define GEMM_SMEM (3 * CHUNK_B)     // 3 stages = 61440 B

template <bool BIAS, bool RELU, bool RES, bool OUTF, bool OUTH>
__global__ __launch_bounds__(256) void gemm_mma(
    const __half* __restrict__ A_, const __half* __restrict__ B_,
    const float* __restrict__ bias, const float* __restrict__ res,
    float* __restrict__ Cf, __half* __restrict__ Ch,
    int M, int N, int K)
{
    extern __shared__ char smem[];
    const uint32_t sb = smem_u32(smem);
    const int tid = threadIdx.x;
    const int lane = tid & 31, wid = tid >> 5;
    const int rowBase = blockIdx.y * 128;
    const int colBase = blockIdx.x * 128;
    const int lr = tid >> 2, ls = tid & 3;

    auto issue = [&](int c) {
        const int k0 = c << 5;
        const uint32_t buf = sb + (uint32_t)(c % 3) * CHUNK_B;
#pragma unroll
        for (int i = 0; i < 2; i++) {
            int r = lr + i * 64;
            uint32_t so = (uint32_t)r * 80 + ls * 16;
            size_t gA = (size_t)(rowBase + r) * K + k0 + ls * 8;
            size_t gB = (size_t)(colBase + r) * K + k0 + ls * 8;
            cp_async16(buf + so,          A_ + gA);
            cp_async16(buf + TILE_B + so, B_ + gB);
        }
        CP_COMMIT();
    };

    const int wm = wid >> 2, wn = wid & 3;
    const int t8 = lane >> 3, r8 = lane & 7;
    const int aR = r8 + ((t8 & 1) << 3);
    const int aK = (t8 & 2) << 2;
    const int bR = r8 + ((t8 >> 1) << 3);
    const int bK = (t8 & 1) << 3;

    float acc[4][4][4];
#pragma unroll
    for (int i = 0; i < 4; i++)
#pragma unroll
        for (int j = 0; j < 4; j++)
#pragma unroll
            for (int q = 0; q < 4; q++) acc[i][j][q] = 0.0f;

    const int nch = K >> 5;
    issue(0); issue(1);

    for (int c = 0; c < nch; c++) {
        if (c + 1 < nch) { CP_WAIT(1); } else { CP_WAIT(0); }
        __syncthreads();
        if (c + 2 < nch) issue(c + 2);

        const uint32_t buf = sb + (uint32_t)(c % 3) * CHUNK_B;
        const uint32_t aB = buf + (uint32_t)(wm * 64 + aR) * 80 + aK * 2;
        const uint32_t bB = buf + TILE_B + (uint32_t)(wn * 32 + bR) * 80 + bK * 2;

#pragma unroll
        for (int ks = 0; ks < 2; ks++) {
            const uint32_t ko = ks * 32;
            uint32_t ah[4][4], bb[2][4];
#pragma unroll
            for (int mt = 0; mt < 4; mt++)
                ldsm_x4(ah[mt], aB + (uint32_t)mt * 16 * 80 + ko);
#pragma unroll
            for (int j = 0; j < 2; j++)
                ldsm_x4(bb[j], bB + (uint32_t)j * 16 * 80 + ko);
#pragma unroll
            for (int mt = 0; mt < 4; mt++) {
#pragma unroll
                for (int nt = 0; nt < 4; nt++)
                    mma_f16(acc[mt][nt], ah[mt], &bb[nt >> 1][(nt & 1) * 2]);
            }
        }
    }

    // ---- epilogue ----
    const int lrr = lane >> 2, lcc = (lane & 3) * 2;
#pragma unroll
    for (int mt = 0; mt < 4; mt++) {
#pragma unroll
        for (int half = 0; half < 2; half++) {
            const int row = rowBase + wm * 64 + mt * 16 + lrr + half * 8;
#pragma unroll
            for (int nt = 0; nt < 4; nt++) {
                const int col = colBase + wn * 32 + nt * 8 + lcc;
                float v0 = acc[mt][nt][half * 2];
                float v1 = acc[mt][nt][half * 2 + 1];
                if (BIAS) { v0 += bias[col]; v1 += bias[col + 1]; }
                if (RES) {
                    const float2 r2 = *reinterpret_cast<const float2*>(
                        &res[(size_t)row * N + col]);
                    v0 += r2.x; v1 += r2.y;
                }
                if (RELU) { v0 = fmaxf(v0, 0.f); v1 = fmaxf(v1, 0.f); }
                const size_t o = (size_t)row * N + col;
                if (OUTF) {
                    float2 w = {v0, v1};
                    *reinterpret_cast<float2*>(&Cf[o]) = w;
                }
                if (OUTH)
                    *reinterpret_cast<__half2*>(&Ch[o]) = __floats2half2_rn(v0, v1);
            }
        }
    }
}

// ---------------------------------------------------------------------------
// fp16 mma flash attention, causal. qkv: [M][3072] (q|k|v packed fp16).
// CTA: 64 queries, 4 warps; key tiles of 64, double-buffered.
// ---------------------------------------------------------------------------
#define AQH 0
#define AKV 9216                     // K buffers at 9216 + pb*9216
#define AVV 27648                    // V buffers at 27648 + pb*9216
#define ATTN_SMEM 46080              // 144B pitch x 64 rows x 5 tiles

__global__ __launch_bounds__(128) void attn_mma(
    const __half* __restrict__ qkv, __half* __restrict__ yh)
{
    extern __shared__ char smem[];
    const uint32_t sb = smem_u32(smem);
    const int tid = threadIdx.x, lane = tid & 31, w = tid >> 5;
    const int bhh = blockIdx.y, b = bhh >> 4, h = bhh & 15;
    const int t0 = blockIdx.x * 64;
    const int last = blockIdx.x;
    const size_t rbase = ((size_t)b * TT) * 3072 + h * 64;

    const int ldr = tid >> 1;
    const int ldsg = (tid & 1) * 4;

    // Q -> smem (group 0)
#pragma unroll
    for (int j = 0; j < 4; j++) {
        size_t g = rbase + (size_t)(t0 + ldr) * 3072 + (ldsg + j) * 8;
        uint32_t so = (uint32_t)ldr * 144 + (ldsg + j) * 16;
        cp_async16(sb + AQH + so, qkv + g);
    }
    CP_COMMIT();

    auto issueKV = [&](int it) {
        const int s0 = it * 64;
        const uint32_t pb = (uint32_t)(it & 1) * 9216;
#pragma unroll
        for (int j = 0; j < 4; j++) {
            size_t gk = rbase + 1024 + (size_t)(s0 + ldr) * 3072 + (ldsg + j) * 8;
            uint32_t so = (uint32_t)ldr * 144 + (ldsg + j) * 16;
            cp_async16(sb + AKV + pb + so, qkv + gk);
            cp_async16(sb + AVV + pb + so, qkv + gk + 1024);
        }
        CP_COMMIT();
    };

    issueKV(0);
    CP_WAIT(1);
    __syncthreads();

    const int t8 = lane >> 3, r8 = lane & 7;
    const int aR = r8 + ((t8 & 1) << 3);
    const int aK = (t8 & 2) << 2;
    const int bR = r8 + ((t8 >> 1) << 3);
    const int bK = (t8 & 1) << 3;

    uint32_t qf[4][4];
#pragma unroll
    for (int kd = 0; kd < 4; kd++)
        ldsm_x4(qf[kd], sb + AQH + (uint32_t)(w * 16 + aR) * 144 + (kd * 16 + aK) * 2);

    float m[2] = {-1e30f, -1e30f}, l[2] = {0.f, 0.f};
    float O[8][4];
#pragma unroll
    for (int i = 0; i < 8; i++)
#pragma unroll
        for (int j = 0; j < 4; j++) O[i][j] = 0.f;

    const int qr0 = w * 16 + (lane >> 2);

    for (int it = 0; it <= last; it++) {
        if (it < last) { issueKV(it + 1); CP_WAIT(1); } else { CP_WAIT(0); }
        __syncthreads();
        const uint32_t pb = (uint32_t)(it & 1) * 9216;

        float s[8][4];
#pragma unroll
        for (int i = 0; i < 8; i++)
#pragma unroll
            for (int j = 0; j < 4; j++) s[i][j] = 0.f;

#pragma unroll
        for (int kd = 0; kd < 4; kd++) {
            uint32_t kb[4][4];
#pragma unroll
            for (int g = 0; g < 4; g++)
                ldsm_x4(kb[g], sb + AKV + pb +
                        (uint32_t)(g * 16 + bR) * 144 + (kd * 16 + bK) * 2);
#pragma unroll
            for (int g = 0; g < 4; g++) {
                mma_f16(s[2 * g],     qf[kd], &kb[g][0]);
                mma_f16(s[2 * g + 1], qf[kd], &kb[g][2]);
            }
        }

#pragma unroll
        for (int nt = 0; nt < 8; nt++)
#pragma unroll
            for (int e = 0; e < 4; e++) s[nt][e] *= 0.03125f;
        if (it == last) {
#pragma unroll
            for (int nt = 0; nt < 8; nt++)
#pragma unroll
                for (int e = 0; e < 4; e++) {
                    int kc = nt * 8 + (lane & 3) * 2 + (e & 1);
                    int qr = qr0 + (e >> 1) * 8;
                    if (kc > qr) s[nt][e] = -1e30f;
                }
        }

        float mn[2] = {m[0], m[1]};
#pragma unroll
        for (int nt = 0; nt < 8; nt++) {
            mn[0] = fmaxf(mn[0], fmaxf(s[nt][0], s[nt][1]));
            mn[1] = fmaxf(mn[1], fmaxf(s[nt][2], s[nt][3]));
        }
#pragma unroll
        for (int i = 0; i < 2; i++) {
            mn[i] = fmaxf(mn[i], __shfl_xor_sync(0xffffffffu, mn[i], 1));
            mn[i] = fmaxf(mn[i], __shfl_xor_sync(0xffffffffu, mn[i], 2));
        }
        float alpha[2];
#pragma unroll
        for (int i = 0; i < 2; i++) {
            alpha[i] = __expf(m[i] - mn[i]);
            m[i] = mn[i];
        }
        float rs[2] = {0.f, 0.f};
#pragma unroll
        for (int nt = 0; nt < 8; nt++) {
#pragma unroll
            for (int e = 0; e < 4; e++) {
                float p = __expf(s[nt][e] - m[e >> 1]);
                s[nt][e] = p;
                rs[e >> 1] += p;
            }
        }
#pragma unroll
        for (int i = 0; i < 2; i++) {
            rs[i] += __shfl_xor_sync(0xffffffffu, rs[i], 1);
            rs[i] += __shfl_xor_sync(0xffffffffu, rs[i], 2);
            l[i] = l[i] * alpha[i] + rs[i];
        }
#pragma unroll
        for (int nt = 0; nt < 8; nt++) {
            O[nt][0] *= alpha[0]; O[nt][1] *= alpha[0];
            O[nt][2] *= alpha[1]; O[nt][3] *= alpha[1];
        }

#pragma unroll
        for (int kk = 0; kk < 4; kk++) {
            uint32_t pa[4];
            pa[0] = pack_h2(s[2 * kk][0],     s[2 * kk][1]);
            pa[1] = pack_h2(s[2 * kk][2],     s[2 * kk][3]);
            pa[2] = pack_h2(s[2 * kk + 1][0], s[2 * kk + 1][1]);
            pa[3] = pack_h2(s[2 * kk + 1][2], s[2 * kk + 1][3]);
#pragma unroll
            for (int dg = 0; dg < 4; dg++) {
                uint32_t vb[4];
                ldsm_x4_t(vb, sb + AVV + pb +
                          (uint32_t)(kk * 16 + aR) * 144 + (dg * 16 + aK) * 2);
                mma_f16(O[dg * 2],     pa, &vb[0]);
                mma_f16(O[dg * 2 + 1], pa, &vb[2]);
            }
        }
        __syncthreads();
    }

    float inv[2] = {1.0f / l[0], 1.0f / l[1]};
    const size_t ob = ((size_t)b * TT) * CC + h * 64;
#pragma unroll
    for (int nt = 0; nt < 8; nt++) {
        int col = nt * 8 + (lane & 3) * 2;
#pragma unroll
        for (int i = 0; i < 2; i++) {
            int row = t0 + qr0 + i * 8;
            size_t o = ob + (size_t)row * CC + col;
            *reinterpret_cast<__half2*>(&yh[o]) =
                __floats2half2_rn(O[nt][2 * i] * inv[i], O[nt][2 * i + 1] * inv[i]);
        }
    }
}

// ---------------------------------------------------------------------------
// Launch sequence
// ---------------------------------------------------------------------------
extern "C" void kernel_launch(void* const* d_in, const int* in_sizes, int n_in,
                              void* d_out, int out_size)
{
    const float* x     = (const float*)d_in[0];
    const float* Wq    = (const float*)d_in[1];
    const float* Wk    = (const float*)d_in[2];
    const float* Wv    = (const float*)d_in[3];
    const float* Wproj = (const float*)d_in[4];
    const float* bproj = (const float*)d_in[5];
    const float* W1    = (const float*)d_in[6];
    const float* b1    = (const float*)d_in[7];
    const float* W2    = (const float*)d_in[8];
    const float* b2    = (const float*)d_in[9];
    float* out = (float*)d_out;

    __half *xh, *Bqkv, *Bp, *B1, *B2, *qkv, *yh, *x2h, *h1h;
    float *x2;
    cudaGetSymbolAddress((void**)&xh,  g_xh);
    cudaGetSymbolAddress((void**)&Bqkv, g_Bqkv);
    cudaGetSymbolAddress((void**)&Bp,  g_Bp);
    cudaGetSymbolAddress((void**)&B1,  g_B1);   cudaGetSymbolAddress((void**)&B2, g_B2);
    cudaGetSymbolAddress((void**)&qkv, g_qkv);
    cudaGetSymbolAddress((void**)&yh,  g_yh);
    cudaGetSymbolAddress((void**)&x2,  g_x2);
    cudaGetSymbolAddress((void**)&x2h, g_x2h);
    cudaGetSymbolAddress((void**)&h1h, g_h1h);

    cudaFuncSetAttribute(gemm_mma<false,false,false,false,true>,
                         cudaFuncAttributeMaxDynamicSharedMemorySize, GEMM_SMEM);
    cudaFuncSetAttribute(gemm_mma<true,false,true,true,true>,
                         cudaFuncAttributeMaxDynamicSharedMemorySize, GEMM_SMEM);
    cudaFuncSetAttribute(gemm_mma<true,true,false,false,true>,
                         cudaFuncAttributeMaxDynamicSharedMemorySize, GEMM_SMEM);
    cudaFuncSetAttribute(gemm_mma<true,false,true,true,false>,
                         cudaFuncAttributeMaxDynamicSharedMemorySize, GEMM_SMEM);
    cudaFuncSetAttribute(attn_mma,
                         cudaFuncAttributeMaxDynamicSharedMemorySize, ATTN_SMEM);

    dim3 tpb(256);

    // Prepass: input conversion + weight transposes
    conv_half<<<(MROWS * CC / 4 + 255) / 256, tpb>>>(x, xh, MROWS * CC / 4);
    transpose_half<<<dim3(2, 32, 16), tpb>>>(Wq, Bqkv, 64, (long)CC * 64, 0,    CC);
    transpose_half<<<dim3(2, 32, 16), tpb>>>(Wk, Bqkv, 64, (long)CC * 64, 1024, CC);
    transpose_half<<<dim3(2, 32, 16), tpb>>>(Wv, Bqkv, 64, (long)CC * 64, 2048, CC);
    transpose_half<<<dim3(32, 32, 1), tpb>>>(Wproj, Bp, CC, 0, 0, CC);
    transpose_half<<<dim3(128, 32, 1), tpb>>>(W1, B1, FF, 0, 0, CC);
    transpose_half<<<dim3(32, 128, 1), tpb>>>(W2, B2, CC, 0, 0, FF);

    // Fused QKV -> qkv fp16
    gemm_mma<false,false,false,false,true><<<dim3(3072 / 128, MROWS / 128), tpb, GEMM_SMEM>>>(
        xh, Bqkv, nullptr, nullptr, nullptr, qkv, MROWS, 3072, CC);

    // Causal attention (tensor cores) -> y fp16
    attn_mma<<<dim3(TT / 64, BB * 16), dim3(128), ATTN_SMEM>>>(qkv, yh);

    // Output projection + bias + residual(x) -> x2 fp32 + fp16
    gemm_mma<true,false,true,true,true><<<dim3(CC / 128, MROWS / 128), tpb, GEMM_SMEM>>>(
        yh, Bp, bproj, x, x2, x2h, MROWS, CC, CC);

    // FF1: relu(x2 @ W1 + b1) -> h1 fp16
    gemm_mma<true,true,false,false,true><<<dim3(FF / 128, MROWS / 128), tpb, GEMM_SMEM>>>(
        x2h, B1, b1, nullptr, nullptr, h1h, MROWS, FF, CC);

    // FF2: h1 @ W2 + b2 + x2 -> out fp32
    gemm_mma<true,false,true,true,false><<<dim3(CC / 128, MROWS / 128), tpb, GEMM_SMEM>>>(
        h1h, B2, b2, x2, out, nullptr, MROWS, CC, FF);
}